// round 1
// baseline (speedup 1.0000x reference)
#include <cuda_runtime.h>

#define NMAX 50000
#define EMAX 800000
#define ETOTMAX (NMAX + EMAX)

// ---------------- scratch (device globals; no allocation allowed) ----------
__device__ float g_h1[NMAX * 256];     // layer-1 features h = x@W1
__device__ float g_hagg[NMAX * 256];   // layer-1 aggregated output (+bias1, pre-ELU)
__device__ float g_asrc1[NMAX * 8];
__device__ float g_adst1[NMAX * 8];
__device__ float g_h2[NMAX * 16];      // layer-2 features elu(hagg)@W2
__device__ float g_asrc2[NMAX];
__device__ float g_adst2[NMAX];
__device__ int   g_cnt[NMAX];
__device__ int   g_off[NMAX + 1];
__device__ int   g_cur[NMAX];
__device__ int   g_csr[ETOTMAX];       // src ids grouped by dst
__device__ int   g_is64;

__device__ __forceinline__ float lrelu(float x) { return x > 0.f ? x : 0.2f * x; }
__device__ __forceinline__ float warp_sum(float v) {
    #pragma unroll
    for (int o = 16; o; o >>= 1) v += __shfl_xor_sync(0xffffffffu, v, o);
    return v;
}
__device__ __forceinline__ float warp_max(float v) {
    #pragma unroll
    for (int o = 16; o; o >>= 1) v = fmaxf(v, __shfl_xor_sync(0xffffffffu, v, o));
    return v;
}

// ---------------- dtype detect: int64 vs int32 edge_index ------------------
__global__ void k_detect(const int* __restrict__ ei32, int twoE) {
    __shared__ int s_any;
    if (threadIdx.x == 0) s_any = 0;
    __syncthreads();
    int n = twoE < 2048 ? twoE : 2048;   // if int64, buffer has 2*twoE words, so safe
    int nz = 0;
    for (int i = 2 * (int)threadIdx.x + 1; i < n; i += 512)
        nz |= (ei32[i] != 0);
    if (nz) atomicOr(&s_any, 1);
    __syncthreads();
    if (threadIdx.x == 0) g_is64 = s_any ? 0 : 1;
}

__global__ void k_zero(int N) {
    int i = blockIdx.x * blockDim.x + threadIdx.x;
    if (i < N) g_cnt[i] = 0;
}

// ---------------- GEMM1: g_h1 = x[M,128] @ W1[128,256] ---------------------
__global__ __launch_bounds__(256) void k_gemm1(const float* __restrict__ A,
                                               const float* __restrict__ B, int M) {
    const int K = 128, N = 256;
    __shared__ float As[16][128];
    __shared__ float Bs[16][64];
    int tid = threadIdx.x;
    int tx = tid & 15, ty = tid >> 4;
    int row0 = blockIdx.y * 128, col0 = blockIdx.x * 64;
    float acc[8][4];
    #pragma unroll
    for (int u = 0; u < 8; u++)
        #pragma unroll
        for (int v = 0; v < 4; v++) acc[u][v] = 0.f;

    for (int k0 = 0; k0 < K; k0 += 16) {
        #pragma unroll
        for (int i = 0; i < 8; i++) {
            int idx = tid + i * 256;
            int r = idx >> 4, c = idx & 15;
            int gr = row0 + r;
            As[c][r] = (gr < M) ? A[gr * K + k0 + c] : 0.f;
        }
        #pragma unroll
        for (int i = 0; i < 4; i++) {
            int idx = tid + i * 256;
            int r = idx >> 6, c = idx & 63;
            Bs[r][c] = B[(k0 + r) * N + col0 + c];
        }
        __syncthreads();
        #pragma unroll
        for (int k = 0; k < 16; k++) {
            float a[8], b[4];
            #pragma unroll
            for (int u = 0; u < 8; u++) a[u] = As[k][ty * 8 + u];
            #pragma unroll
            for (int v = 0; v < 4; v++) b[v] = Bs[k][tx * 4 + v];
            #pragma unroll
            for (int u = 0; u < 8; u++)
                #pragma unroll
                for (int v = 0; v < 4; v++) acc[u][v] = fmaf(a[u], b[v], acc[u][v]);
        }
        __syncthreads();
    }
    #pragma unroll
    for (int u = 0; u < 8; u++) {
        int gr = row0 + ty * 8 + u;
        if (gr < M) {
            float4 o = make_float4(acc[u][0], acc[u][1], acc[u][2], acc[u][3]);
            *(float4*)&g_h1[(size_t)gr * 256 + col0 + tx * 4] = o;
        }
    }
}

// ---------------- per-node attention logits, layer 1 -----------------------
__global__ __launch_bounds__(256) void k_att1(const float* __restrict__ att_src,
                                              const float* __restrict__ att_dst, int N) {
    int n = (blockIdx.x * blockDim.x + threadIdx.x) >> 5;
    int lane = threadIdx.x & 31;
    if (n >= N) return;
    const float* hr = g_h1 + (size_t)n * 256;
    #pragma unroll
    for (int h = 0; h < 8; h++) {
        float v = hr[h * 32 + lane];
        float ps = warp_sum(v * att_src[h * 32 + lane]);
        float pd = warp_sum(v * att_dst[h * 32 + lane]);
        if (lane == 0) { g_asrc1[n * 8 + h] = ps; g_adst1[n * 8 + h] = pd; }
    }
}

// ---------------- CSR build -------------------------------------------------
__global__ void k_hist(const void* __restrict__ ei, int E, int N) {
    int i = blockIdx.x * blockDim.x + threadIdx.x;
    if (i >= E + N) return;
    int d;
    if (i < E) {
        d = g_is64 ? (int)((const long long*)ei)[E + i]
                   : ((const int*)ei)[E + i];
    } else {
        d = i - E;
    }
    atomicAdd(&g_cnt[d], 1);
}

__global__ __launch_bounds__(1024) void k_scan(int N) {
    __shared__ int sd[1024];
    int tid = threadIdx.x;
    int chunk = (N + 1023) >> 10;
    int b = tid * chunk;
    int e = b + chunk; if (e > N) e = N;
    if (b > N) b = N;
    int loc = 0;
    for (int i = b; i < e; i++) loc += g_cnt[i];
    sd[tid] = loc;
    __syncthreads();
    for (int s = 1; s < 1024; s <<= 1) {
        int v = (tid >= s) ? sd[tid - s] : 0;
        __syncthreads();
        sd[tid] += v;
        __syncthreads();
    }
    int run = (tid == 0) ? 0 : sd[tid - 1];
    for (int i = b; i < e; i++) {
        g_off[i] = run; g_cur[i] = run;
        run += g_cnt[i];
    }
    if (tid == 1023) g_off[N] = sd[1023];
}

__global__ void k_scatter(const void* __restrict__ ei, int E, int N) {
    int i = blockIdx.x * blockDim.x + threadIdx.x;
    if (i >= E + N) return;
    int s, d;
    if (i < E) {
        if (g_is64) {
            const long long* p = (const long long*)ei;
            s = (int)p[i]; d = (int)p[E + i];
        } else {
            const int* p = (const int*)ei;
            s = p[i]; d = p[E + i];
        }
    } else {
        s = d = i - E;
    }
    int pos = atomicAdd(&g_cur[d], 1);
    g_csr[pos] = s;
}

// ---------------- layer-1 softmax + aggregation (warp per dst) -------------
__global__ __launch_bounds__(256) void k_agg1(const float* __restrict__ bias1, int N) {
    int d = (blockIdx.x * blockDim.x + threadIdx.x) >> 5;
    int lane = threadIdx.x & 31;
    if (d >= N) return;
    int beg = g_off[d], end = g_off[d + 1];
    int h = lane & 7, eg = lane >> 3;      // lane = eg*8 + h
    float ad = g_adst1[d * 8 + h];

    float m = -1e30f;
    for (int e = beg + eg; e < end; e += 4) {
        int s = g_csr[e];
        m = fmaxf(m, lrelu(g_asrc1[s * 8 + h] + ad));
    }
    m = fmaxf(m, __shfl_xor_sync(0xffffffffu, m, 8));
    m = fmaxf(m, __shfl_xor_sync(0xffffffffu, m, 16));

    float sum = 0.f;
    for (int e = beg + eg; e < end; e += 4) {
        int s = g_csr[e];
        sum += __expf(lrelu(g_asrc1[s * 8 + h] + ad) - m);
    }
    sum += __shfl_xor_sync(0xffffffffu, sum, 8);
    sum += __shfl_xor_sync(0xffffffffu, sum, 16);
    float inv = 1.f / (sum + 1e-16f);

    float acc[8];
    #pragma unroll
    for (int j = 0; j < 8; j++) acc[j] = 0.f;

    for (int e = beg; e < end; e++) {
        int s = g_csr[e];
        float w = 0.f;
        if (lane < 8) {   // lane<8 => eg=0, h=lane: ad/m/inv are this head's values
            float l = lrelu(g_asrc1[s * 8 + lane] + ad);
            w = __expf(l - m) * inv;
        }
        const float* hp = g_h1 + (size_t)s * 256 + lane;
        #pragma unroll
        for (int j = 0; j < 8; j++) {
            float wj = __shfl_sync(0xffffffffu, w, j);
            acc[j] = fmaf(hp[j * 32], wj, acc[j]);
        }
    }
    float* op = g_hagg + (size_t)d * 256 + lane;
    #pragma unroll
    for (int j = 0; j < 8; j++) op[j * 32] = acc[j] + bias1[j * 32 + lane];
}

// ---------------- GEMM2 (elu on the fly) + layer-2 logits ------------------
__global__ __launch_bounds__(256) void k_gemm2(const float* __restrict__ W2,
                                               const float* __restrict__ as2,
                                               const float* __restrict__ ad2, int N) {
    __shared__ float sh[16][260];
    __shared__ float sw[256 * 16];
    int tid = threadIdx.x;
    int row = tid >> 4, col = tid & 15;
    int n0 = blockIdx.x * 16;

    #pragma unroll
    for (int i = 0; i < 16; i++) sw[tid + i * 256] = W2[tid + i * 256];
    for (int i = tid; i < 16 * 256; i += 256) {
        int r = i >> 8, c = i & 255;
        int n = n0 + r;
        float v = (n < N) ? g_hagg[(size_t)n * 256 + c] : 0.f;
        sh[r][c] = v > 0.f ? v : expm1f(v);
    }
    __syncthreads();

    float acc = 0.f;
    #pragma unroll 8
    for (int k = 0; k < 256; k++) acc = fmaf(sh[row][k], sw[k * 16 + col], acc);

    float ps = acc * as2[col];
    float pd = acc * ad2[col];
    #pragma unroll
    for (int o = 8; o; o >>= 1) {
        ps += __shfl_xor_sync(0xffffffffu, ps, o);
        pd += __shfl_xor_sync(0xffffffffu, pd, o);
    }
    int n = n0 + row;
    if (n < N) {
        g_h2[n * 16 + col] = acc;
        if (col == 0) { g_asrc2[n] = ps; g_adst2[n] = pd; }
    }
}

// ---------------- layer-2 softmax + aggregation (warp per dst) -------------
__global__ __launch_bounds__(256) void k_agg2(const float* __restrict__ bias2,
                                              float* __restrict__ out, int N) {
    int d = (blockIdx.x * blockDim.x + threadIdx.x) >> 5;
    int lane = threadIdx.x & 31;
    if (d >= N) return;
    int beg = g_off[d], end = g_off[d + 1];
    float ad = g_adst2[d];

    float m = -1e30f;
    for (int e = beg + lane; e < end; e += 32)
        m = fmaxf(m, lrelu(g_asrc2[g_csr[e]] + ad));
    m = warp_max(m);

    float sum = 0.f;
    for (int e = beg + lane; e < end; e += 32)
        sum += __expf(lrelu(g_asrc2[g_csr[e]] + ad) - m);
    sum = warp_sum(sum);
    float inv = 1.f / (sum + 1e-16f);

    float acc = 0.f;
    for (int e = beg; e < end; e++) {
        int s = g_csr[e];
        float w = 0.f;
        if (lane == 0) w = __expf(lrelu(g_asrc2[s] + ad) - m) * inv;
        w = __shfl_sync(0xffffffffu, w, 0);
        if (lane < 16) acc = fmaf(g_h2[s * 16 + lane], w, acc);
    }
    if (lane < 16) out[d * 16 + lane] = acc + bias2[lane];
}

// ---------------- launch ----------------------------------------------------
extern "C" void kernel_launch(void* const* d_in, const int* in_sizes, int n_in,
                              void* d_out, int out_size) {
    const float* x   = (const float*)d_in[0];
    const void*  ei  = d_in[1];
    const float* W1  = (const float*)d_in[2];
    const float* as1 = (const float*)d_in[3];
    const float* ad1 = (const float*)d_in[4];
    const float* b1  = (const float*)d_in[5];
    const float* W2  = (const float*)d_in[6];
    const float* as2 = (const float*)d_in[7];
    const float* ad2 = (const float*)d_in[8];
    const float* b2  = (const float*)d_in[9];
    float* out = (float*)d_out;

    int N = in_sizes[0] / 128;   // 50000
    int E = in_sizes[1] / 2;     // 800000 (element count is dtype-independent)
    int tot = E + N;

    k_zero<<<(N + 255) / 256, 256>>>(N);
    k_detect<<<1, 256>>>((const int*)ei, in_sizes[1]);

    dim3 g1(4, (N + 127) / 128);
    k_gemm1<<<g1, 256>>>(x, W1, N);
    k_att1<<<(N * 32 + 255) / 256, 256>>>(as1, ad1, N);

    k_hist<<<(tot + 255) / 256, 256>>>(ei, E, N);
    k_scan<<<1, 1024>>>(N);
    k_scatter<<<(tot + 255) / 256, 256>>>(ei, E, N);

    k_agg1<<<(N * 32 + 255) / 256, 256>>>(b1, N);
    k_gemm2<<<(N + 15) / 16, 256>>>(W2, as2, ad2, N);
    k_agg2<<<(N * 32 + 255) / 256, 256>>>(b2, out, N);
}

// round 3
// speedup vs baseline: 1.0799x; 1.0799x over previous
#include <cuda_runtime.h>
#include <cuda_fp16.h>

#define NMAX 50000
#define EMAX 800000
#define ETOTMAX (NMAX + EMAX)

// ---------------- scratch (device globals; no allocation allowed) ----------
__device__ __half g_h1h[NMAX * 256];   // layer-1 features (fp16, for gather)
__device__ float g_hagg[NMAX * 256];   // layer-1 aggregated output (+bias1, pre-ELU)
__device__ float g_asrc1[NMAX * 8];
__device__ float g_adst1[NMAX * 8];
__device__ float g_h2[NMAX * 16];
__device__ float g_asrc2[NMAX];
__device__ float g_adst2[NMAX];
__device__ int   g_cnt[NMAX];
__device__ int   g_off[NMAX + 1];
__device__ int   g_cur[NMAX];
__device__ int   g_csr[ETOTMAX];
__device__ int   g_is64;

__device__ __forceinline__ float lrelu(float x) { return x > 0.f ? x : 0.2f * x; }
__device__ __forceinline__ float warp_sum(float v) {
    #pragma unroll
    for (int o = 16; o; o >>= 1) v += __shfl_xor_sync(0xffffffffu, v, o);
    return v;
}
__device__ __forceinline__ float warp_max(float v) {
    #pragma unroll
    for (int o = 16; o; o >>= 1) v = fmaxf(v, __shfl_xor_sync(0xffffffffu, v, o));
    return v;
}

// ---------------- dtype detect: int64 vs int32 edge_index ------------------
__global__ void k_detect(const int* __restrict__ ei32, int twoE) {
    __shared__ int s_any;
    if (threadIdx.x == 0) s_any = 0;
    __syncthreads();
    int n = twoE < 2048 ? twoE : 2048;
    int nz = 0;
    for (int i = 2 * (int)threadIdx.x + 1; i < n; i += 512)
        nz |= (ei32[i] != 0);
    if (nz) atomicOr(&s_any, 1);
    __syncthreads();
    if (threadIdx.x == 0) g_is64 = s_any ? 0 : 1;
}

__global__ void k_zero(int N) {
    int i = blockIdx.x * blockDim.x + threadIdx.x;
    if (i < N) g_cnt[i] = 0;
}

// ---------------- GEMM1 + fused att logits ---------------------------------
// block: 128 rows x 128 cols (= 4 heads). 256 threads, 8x8 microtile.
__global__ __launch_bounds__(256, 2) void k_gemm1(const float* __restrict__ A,
                                                  const float* __restrict__ B,
                                                  const float* __restrict__ att_s,
                                                  const float* __restrict__ att_d,
                                                  int M) {
    __shared__ float As[8][132];
    __shared__ float Bs[8][128];
    int tid = threadIdx.x;
    int tx = tid & 15, ty = tid >> 4;
    int row0 = blockIdx.y * 128, col0 = blockIdx.x * 128;

    float acc[8][8];
    #pragma unroll
    for (int u = 0; u < 8; u++)
        #pragma unroll
        for (int v = 0; v < 8; v++) acc[u][v] = 0.f;

    int ar = tid >> 1, acq = (tid & 1) * 4;
    int br = tid >> 5, bc = (tid & 31) * 4;

    for (int k0 = 0; k0 < 128; k0 += 8) {
        float4 av = make_float4(0.f, 0.f, 0.f, 0.f);
        if (row0 + ar < M) av = *(const float4*)&A[(size_t)(row0 + ar) * 128 + k0 + acq];
        float4 bv = *(const float4*)&B[(size_t)(k0 + br) * 256 + col0 + bc];
        __syncthreads();
        As[acq + 0][ar] = av.x; As[acq + 1][ar] = av.y;
        As[acq + 2][ar] = av.z; As[acq + 3][ar] = av.w;
        *(float4*)&Bs[br][bc] = bv;
        __syncthreads();
        #pragma unroll
        for (int k = 0; k < 8; k++) {
            float a[8], b[8];
            *(float4*)&a[0] = *(float4*)&As[k][ty * 8];
            *(float4*)&a[4] = *(float4*)&As[k][ty * 8 + 4];
            *(float4*)&b[0] = *(float4*)&Bs[k][tx * 8];
            *(float4*)&b[4] = *(float4*)&Bs[k][tx * 8 + 4];
            #pragma unroll
            for (int u = 0; u < 8; u++)
                #pragma unroll
                for (int v = 0; v < 8; v++) acc[u][v] = fmaf(a[u], b[v], acc[u][v]);
        }
        __syncthreads();
    }

    // fused attention logits: head of this thread's 8 cols
    int hb = (col0 >> 5) + (tx >> 2);
    float asr[8], adr[8];
    #pragma unroll
    for (int v = 0; v < 8; v++) {
        asr[v] = att_s[hb * 32 + (tx & 3) * 8 + v];
        adr[v] = att_d[hb * 32 + (tx & 3) * 8 + v];
    }

    #pragma unroll
    for (int u = 0; u < 8; u++) {
        int grow = row0 + ty * 8 + u;
        float ps = 0.f, pd = 0.f;
        #pragma unroll
        for (int v = 0; v < 8; v++) {
            ps = fmaf(acc[u][v], asr[v], ps);
            pd = fmaf(acc[u][v], adr[v], pd);
        }
        ps += __shfl_xor_sync(0xffffffffu, ps, 1);
        ps += __shfl_xor_sync(0xffffffffu, ps, 2);
        pd += __shfl_xor_sync(0xffffffffu, pd, 1);
        pd += __shfl_xor_sync(0xffffffffu, pd, 2);
        if (grow < M) {
            if ((tx & 3) == 0) {
                g_asrc1[grow * 8 + hb] = ps;
                g_adst1[grow * 8 + hb] = pd;
            }
            // fp16 store of 8 cols (16 bytes)
            __half2 p0 = __floats2half2_rn(acc[u][0], acc[u][1]);
            __half2 p1 = __floats2half2_rn(acc[u][2], acc[u][3]);
            __half2 p2 = __floats2half2_rn(acc[u][4], acc[u][5]);
            __half2 p3 = __floats2half2_rn(acc[u][6], acc[u][7]);
            uint4 pk;
            pk.x = *(unsigned*)&p0; pk.y = *(unsigned*)&p1;
            pk.z = *(unsigned*)&p2; pk.w = *(unsigned*)&p3;
            *(uint4*)&g_h1h[(size_t)grow * 256 + col0 + tx * 8] = pk;
        }
    }
}

// ---------------- CSR build -------------------------------------------------
__global__ void k_hist(const void* __restrict__ ei, int E, int N) {
    int i = blockIdx.x * blockDim.x + threadIdx.x;
    if (i >= E + N) return;
    int d;
    if (i < E) {
        d = g_is64 ? (int)((const long long*)ei)[E + i]
                   : ((const int*)ei)[E + i];
    } else {
        d = i - E;
    }
    atomicAdd(&g_cnt[d], 1);
}

__global__ __launch_bounds__(1024) void k_scan(int N) {
    __shared__ int sd[1024];
    int tid = threadIdx.x;
    int chunk = (N + 1023) >> 10;
    int b = tid * chunk;
    int e = b + chunk; if (e > N) e = N;
    if (b > N) b = N;
    int loc = 0;
    for (int i = b; i < e; i++) loc += g_cnt[i];
    sd[tid] = loc;
    __syncthreads();
    for (int s = 1; s < 1024; s <<= 1) {
        int v = (tid >= s) ? sd[tid - s] : 0;
        __syncthreads();
        sd[tid] += v;
        __syncthreads();
    }
    int run = (tid == 0) ? 0 : sd[tid - 1];
    for (int i = b; i < e; i++) {
        g_off[i] = run; g_cur[i] = run;
        run += g_cnt[i];
    }
    if (tid == 1023) g_off[N] = sd[1023];
}

__global__ void k_scatter(const void* __restrict__ ei, int E, int N) {
    int i = blockIdx.x * blockDim.x + threadIdx.x;
    if (i >= E + N) return;
    int s, d;
    if (i < E) {
        if (g_is64) {
            const long long* p = (const long long*)ei;
            s = (int)p[i]; d = (int)p[E + i];
        } else {
            const int* p = (const int*)ei;
            s = p[i]; d = p[E + i];
        }
    } else {
        s = d = i - E;
    }
    int pos = atomicAdd(&g_cur[d], 1);
    g_csr[pos] = s;
}

// ---------------- layer-1 softmax + aggregation (warp per dst) -------------
__global__ __launch_bounds__(256) void k_agg1(const float* __restrict__ bias1, int N) {
    int d = (blockIdx.x * blockDim.x + threadIdx.x) >> 5;
    int lane = threadIdx.x & 31;
    if (d >= N) return;
    int beg = g_off[d], end = g_off[d + 1];
    int h = lane & 7, eg = lane >> 3;
    float adv = g_adst1[d * 8 + h];

    float m = -1e30f;
    for (int e = beg + eg; e < end; e += 4)
        m = fmaxf(m, lrelu(g_asrc1[g_csr[e] * 8 + h] + adv));
    m = fmaxf(m, __shfl_xor_sync(0xffffffffu, m, 8));
    m = fmaxf(m, __shfl_xor_sync(0xffffffffu, m, 16));

    float sum = 0.f;
    for (int e = beg + eg; e < end; e += 4)
        sum += __expf(lrelu(g_asrc1[g_csr[e] * 8 + h] + adv) - m);
    sum += __shfl_xor_sync(0xffffffffu, sum, 8);
    sum += __shfl_xor_sync(0xffffffffu, sum, 16);
    float inv = 1.f / (sum + 1e-16f);

    float2 acc[4];
    #pragma unroll
    for (int j = 0; j < 4; j++) acc[j] = make_float2(0.f, 0.f);
    int hj[4];
    #pragma unroll
    for (int j = 0; j < 4; j++) hj[j] = j * 2 + (lane >> 4);

    const __half2* base = (const __half2*)g_h1h;
    for (int e = beg; e < end; e++) {
        int s = g_csr[e];
        float w = 0.f;
        if (lane < 8)
            w = __expf(lrelu(g_asrc1[s * 8 + lane] + adv) - m) * inv;
        const __half2* hp = base + (size_t)s * 128 + lane;
        #pragma unroll
        for (int j = 0; j < 4; j++) {
            float wj = __shfl_sync(0xffffffffu, w, hj[j]);
            float2 f = __half22float2(hp[j * 32]);
            acc[j].x = fmaf(f.x, wj, acc[j].x);
            acc[j].y = fmaf(f.y, wj, acc[j].y);
        }
    }
    float* op = g_hagg + (size_t)d * 256;
    #pragma unroll
    for (int j = 0; j < 4; j++) {
        int c = j * 64 + lane * 2;
        float2 bv = *(const float2*)&bias1[c];
        float2 o = make_float2(acc[j].x + bv.x, acc[j].y + bv.y);
        *(float2*)&op[c] = o;
    }
}

// ---------------- GEMM2 (elu on the fly) + layer-2 logits ------------------
__global__ __launch_bounds__(256) void k_gemm2(const float* __restrict__ W2,
                                               const float* __restrict__ as2,
                                               const float* __restrict__ ad2, int N) {
    __shared__ float sh[16][260];
    __shared__ float sw[256 * 16];
    int tid = threadIdx.x;
    int row = tid >> 4, col = tid & 15;
    int n0 = blockIdx.x * 16;

    #pragma unroll
    for (int i = 0; i < 16; i++) sw[tid + i * 256] = W2[tid + i * 256];
    for (int i = tid; i < 16 * 256; i += 256) {
        int r = i >> 8, c = i & 255;
        int n = n0 + r;
        float v = (n < N) ? g_hagg[(size_t)n * 256 + c] : 0.f;
        sh[r][c] = v > 0.f ? v : expm1f(v);
    }
    __syncthreads();

    float acc = 0.f;
    #pragma unroll 8
    for (int k = 0; k < 256; k++) acc = fmaf(sh[row][k], sw[k * 16 + col], acc);

    float ps = acc * as2[col];
    float pd = acc * ad2[col];
    #pragma unroll
    for (int o = 8; o; o >>= 1) {
        ps += __shfl_xor_sync(0xffffffffu, ps, o);
        pd += __shfl_xor_sync(0xffffffffu, pd, o);
    }
    int n = n0 + row;
    if (n < N) {
        g_h2[n * 16 + col] = acc;
        if (col == 0) { g_asrc2[n] = ps; g_adst2[n] = pd; }
    }
}

// ---------------- layer-2 softmax + aggregation (warp per dst) -------------
__global__ __launch_bounds__(256) void k_agg2(const float* __restrict__ bias2,
                                              float* __restrict__ out, int N) {
    int d = (blockIdx.x * blockDim.x + threadIdx.x) >> 5;
    int lane = threadIdx.x & 31;
    if (d >= N) return;
    int beg = g_off[d], end = g_off[d + 1];
    float ad = g_adst2[d];

    float m = -1e30f;
    for (int e = beg + lane; e < end; e += 32)
        m = fmaxf(m, lrelu(g_asrc2[g_csr[e]] + ad));
    m = warp_max(m);

    float sum = 0.f;
    for (int e = beg + lane; e < end; e += 32)
        sum += __expf(lrelu(g_asrc2[g_csr[e]] + ad) - m);
    sum = warp_sum(sum);
    float inv = 1.f / (sum + 1e-16f);

    float acc = 0.f;
    for (int e = beg; e < end; e++) {
        int s = g_csr[e];
        float w = 0.f;
        if (lane == 0) w = __expf(lrelu(g_asrc2[s] + ad) - m) * inv;
        w = __shfl_sync(0xffffffffu, w, 0);
        if (lane < 16) acc = fmaf(g_h2[s * 16 + lane], w, acc);
    }
    if (lane < 16) out[d * 16 + lane] = acc + bias2[lane];
}

// ---------------- launch ----------------------------------------------------
extern "C" void kernel_launch(void* const* d_in, const int* in_sizes, int n_in,
                              void* d_out, int out_size) {
    const float* x   = (const float*)d_in[0];
    const void*  ei  = d_in[1];
    const float* W1  = (const float*)d_in[2];
    const float* as1 = (const float*)d_in[3];
    const float* ad1 = (const float*)d_in[4];
    const float* b1  = (const float*)d_in[5];
    const float* W2  = (const float*)d_in[6];
    const float* as2 = (const float*)d_in[7];
    const float* ad2 = (const float*)d_in[8];
    const float* b2  = (const float*)d_in[9];
    float* out = (float*)d_out;

    int N = in_sizes[0] / 128;
    int E = in_sizes[1] / 2;
    int tot = E + N;

    k_zero<<<(N + 255) / 256, 256>>>(N);
    k_detect<<<1, 256>>>((const int*)ei, in_sizes[1]);

    dim3 g1(2, (N + 127) / 128);
    k_gemm1<<<g1, 256>>>(x, W1, as1, ad1, N);

    k_hist<<<(tot + 255) / 256, 256>>>(ei, E, N);
    k_scan<<<1, 1024>>>(N);
    k_scatter<<<(tot + 255) / 256, 256>>>(ei, E, N);

    k_agg1<<<(N * 32 + 255) / 256, 256>>>(b1, N);
    k_gemm2<<<(N + 15) / 16, 256>>>(W2, as2, ad2, N);
    k_agg2<<<(N * 32 + 255) / 256, 256>>>(b2, out, N);
}